// round 12
// baseline (speedup 1.0000x reference)
#include <cuda_runtime.h>
#include <cuda_fp16.h>

// Problem constants (fixed by the reference):
// B=4, N=8, H=512, W=512, C=65536, SCALING=10, EPS=1e-10, ITERS=17
// attrs layout: [bbox(4), area(1), angle(1), pca_big(1), pca_small(1), hu(7)] = 15 cols
#define NB 4
#define NN 8
#define NC 65536
#define NATTR 15
#define TOT (NB * NN * NC)        // 2,097,152 elements
#define NPIX (NB * NN * 512 * 512)
#define EPSF 1e-10f
#define CK 16384                  // smem chunk size -> 4 chunks per row
#define CT 1024                   // resolve kernel threads
#define NCHUNK (TOT / CK)         // 128 blocks -> 1/SM, all co-resident
#define GSLICE 4                  // gather slices per row -> 128 blocks, 1 wave

// Packed state: low 32b = float s (partial ancestor sum), high 32b = int p.
__device__ unsigned long long g_sp[TOT];            // 16 MB
__device__ __align__(16) __half g_val[TOT];         // 4 MB final values (*0.1, fp16)
__device__ unsigned int g_bar;                      // grid barrier counter

__device__ __forceinline__ unsigned long long pack_sp(float s, int p) {
    return (unsigned long long)(unsigned int)__float_as_int(s)
         | ((unsigned long long)(unsigned int)p << 32);
}
__device__ __forceinline__ float sp_s(unsigned long long v) {
    return __int_as_float((int)(unsigned int)v);
}
__device__ __forceinline__ int sp_p(unsigned long long v) {
    return (int)(v >> 32);
}

// ---------------------------------------------------------------------------
// Phase 1: w = diff * sigmoid(_log_scaling(attrs) . weight[n] + bias[n]);
// init packed state {w, parent}; reset the grid barrier counter (stream
// order guarantees this precedes resolve_kernel on every graph replay).
// ---------------------------------------------------------------------------
__global__ void __launch_bounds__(256) score_kernel(
    const float* __restrict__ diff, const float* __restrict__ attrs,
    const float* __restrict__ weight, const float* __restrict__ bias,
    const int* __restrict__ parent)
{
    __shared__ float sa[256 * NATTR];
    const int base = blockIdx.x * 256;
    if (blockIdx.x == 0 && threadIdx.x == 0) g_bar = 0u;

    const float4* ap = (const float4*)(attrs + (size_t)base * NATTR);
    #pragma unroll
    for (int k = threadIdx.x; k < 256 * NATTR / 4; k += 256)
        ((float4*)sa)[k] = ap[k];
    __syncthreads();

    const int idx = base + threadIdx.x;
    const float* f = &sa[threadIdx.x * NATTR];
    const int n = (idx >> 16) & (NN - 1);      // all 256 elems share one n
    const float* wg = weight + n * 17;

    // feats: [bbox0..3, log(area), signed-log f[6..14] (9), lshape, cos, sin]
    float logit = bias[n];
    logit += f[0] * wg[0] + f[1] * wg[1] + f[2] * wg[2] + f[3] * wg[3];
    logit += __logf(f[4]) * wg[4];
    #pragma unroll
    for (int k = 0; k < 9; k++) {
        float x = f[6 + k];
        float sg = (float)((x > 0.0f) - (x < 0.0f));
        logit += sg * __logf(fabsf(x) + EPSF) * wg[5 + k];
    }
    logit += __fdividef(__fsqrt_rn(f[7]), __fsqrt_rn(f[6]) + EPSF) * wg[14];
    float sn, cs;
    __sincosf(f[5], &sn, &cs);
    logit += cs * wg[15] + sn * wg[16];

    const float score = __fdividef(1.0f, 1.0f + __expf(-logit));
    g_sp[idx] = pack_sp(diff[idx] * score, parent[idx]);
}

// ---------------------------------------------------------------------------
// Phase 2 (fused chunk compression + extract):
//  a) load own 16384-elem chunk to smem; racy path-compressing chain walks
//     (8B untorn smem ops; entries only improve) until every pointer escapes
//     the chunk. parent[i] < i guarantees termination.
//  b) publish compressed g_sp (skip the top chunk of each row: with strictly
//     decreasing chunk targets it is never gathered).
//  c) ONE device-wide barrier (128 blocks, 1 block/SM, all co-resident in
//     wave 1 -> deadlock-free; fence+arrive+spin+syncthreads).
//  d) resolve own elements FROM SMEM with <= 3 predicated global hops
//     through lower chunks' compressed entries; write fp16 finals (*0.1).
// ---------------------------------------------------------------------------
__global__ void __launch_bounds__(CT) resolve_kernel() {
    extern __shared__ unsigned long long sp[];
    const int gbase = blockIdx.x * CK;
    const int cbase = gbase & (NC - 1);        // row-local chunk base
    const int clim  = cbase + CK;
    const int rowbase = gbase & ~(NC - 1);

    for (int j = threadIdx.x; j < CK / 2; j += CT)
        ((ulonglong2*)sp)[j] = ((const ulonglong2*)&g_sp[gbase])[j];
    __syncthreads();

    // racy path-compressing chain walks (ascending order -> mostly 1 hop)
    #pragma unroll
    for (int j = 0; j < CK / CT; j++) {
        const int e = threadIdx.x + j * CT;
        unsigned long long v = sp[e];
        float s = sp_s(v);
        int   p = sp_p(v);
        while (p >= cbase && p < clim) {       // in-chunk (excludes NC)
            unsigned long long q = sp[p - cbase];
            s += sp_s(q);
            p  = sp_p(q);                      // strictly decreasing
        }
        sp[e] = pack_sp(s, p);
    }
    __syncthreads();

    // publish compressed chunk (top chunk of each row is never gathered)
    if ((blockIdx.x & 3) != 3) {
        for (int j = threadIdx.x; j < CK / 2; j += CT)
            ((ulonglong2*)&g_sp[gbase])[j] = ((const ulonglong2*)sp)[j];
    }

    // device-wide barrier
    __syncthreads();
    if (threadIdx.x == 0) {
        __threadfence();
        atomicAdd(&g_bar, 1u);
        while (atomicAdd(&g_bar, 0u) < (unsigned)gridDim.x) __nanosleep(64);
    }
    __syncthreads();

    // resolve own elements from smem; <=3 hops through lower chunks
    #pragma unroll
    for (int j = 0; j < CK / CT; j++) {
        const int e = threadIdx.x + j * CT;
        unsigned long long v = sp[e];
        float s = sp_s(v);
        int   p = sp_p(v);
        #pragma unroll
        for (int it = 0; it < 3; it++) {
            if (p != NC) {
                unsigned long long q = __ldcg(&g_sp[rowbase + p]);
                s += sp_s(q);
                p  = sp_p(q);
            }
        }
        g_val[gbase + e] = __float2half_rn(s * 0.1f);
    }
}

// ---------------------------------------------------------------------------
// Phase 3: smem-windowed gather. One block per (row, slice); full 65536-entry
// fp16 window (128 KB) in dynamic smem. 1024 threads (32 warps/SM); 128
// blocks = one clean wave.
// ---------------------------------------------------------------------------
__global__ void __launch_bounds__(1024) gather_kernel(
    const int* __restrict__ pix2cc, float* __restrict__ out)
{
    extern __shared__ __half sv[];
    const int row = blockIdx.x >> 2;                 // GSLICE = 4
    const int pbase = blockIdx.x << 16;              // 65536 pixels per block

    const uint4* vals = (const uint4*)(g_val + (row << 16));
    #pragma unroll
    for (int i = threadIdx.x; i < NC * 2 / 16; i += 1024)
        ((uint4*)sv)[i] = __ldcg(&vals[i]);
    __syncthreads();

    const int4* pc = (const int4*)(pix2cc + pbase);
    float4* op = (float4*)(out + pbase);
    #pragma unroll
    for (int i = threadIdx.x; i < 65536 / 4; i += 1024) {
        const int4 cc = __ldg(&pc[i]);
        float4 o;
        o.x = __half2float(sv[cc.x]);
        o.y = __half2float(sv[cc.y]);
        o.z = __half2float(sv[cc.z]);
        o.w = __half2float(sv[cc.w]);
        op[i] = o;
    }
}

// ---------------------------------------------------------------------------
extern "C" void kernel_launch(void* const* d_in, const int* in_sizes, int n_in,
                              void* d_out, int out_size) {
    const float* diff   = (const float*)d_in[0];
    const float* attrs  = (const float*)d_in[1];
    const float* weight = (const float*)d_in[2];
    const float* bias   = (const float*)d_in[3];
    const int*   parent = (const int*)d_in[4];
    const int*   pix2cc = (const int*)d_in[5];
    float* out = (float*)d_out;

    const int chunk_smem  = CK * 8;       // 128 KB
    const int gather_smem = NC * 2;       // 128 KB
    cudaFuncSetAttribute(resolve_kernel,
                         cudaFuncAttributeMaxDynamicSharedMemorySize, chunk_smem);
    cudaFuncSetAttribute(gather_kernel,
                         cudaFuncAttributeMaxDynamicSharedMemorySize, gather_smem);

    score_kernel<<<TOT / 256, 256>>>(diff, attrs, weight, bias, parent);
    resolve_kernel<<<NCHUNK, CT, chunk_smem>>>();
    gather_kernel<<<NB * NN * GSLICE, 1024, gather_smem>>>(pix2cc, out);
}

// round 13
// speedup vs baseline: 1.0837x; 1.0837x over previous
#include <cuda_runtime.h>
#include <cuda_fp16.h>

// Problem constants (fixed by the reference):
// B=4, N=8, H=512, W=512, C=65536, SCALING=10, EPS=1e-10, ITERS=17
// attrs layout: [bbox(4), area(1), angle(1), pca_big(1), pca_small(1), hu(7)] = 15 cols
#define NB 4
#define NN 8
#define NC 65536
#define NATTR 15
#define TOT (NB * NN * NC)        // 2,097,152 elements
#define NPIX (NB * NN * 512 * 512)
#define EPSF 1e-10f
#define CK 16384                  // smem chunk size -> 4 chunks per row
#define CT 1024                   // chunk kernel threads
#define GSLICE 4                  // gather slices per row -> 128 blocks, 1 wave
#define TOT3 (TOT * 3 / 4)        // elements in chunks 1..3 of each row

// Packed state: low 32b = float s (partial ancestor sum), high 32b = int p.
__device__ unsigned long long g_sp[TOT];            // 16 MB
__device__ __align__(16) __half g_val[TOT];         // 4 MB final values (*0.1, fp16)

__device__ __forceinline__ unsigned long long pack_sp(float s, int p) {
    return (unsigned long long)(unsigned int)__float_as_int(s)
         | ((unsigned long long)(unsigned int)p << 32);
}
__device__ __forceinline__ float sp_s(unsigned long long v) {
    return __int_as_float((int)(unsigned int)v);
}
__device__ __forceinline__ int sp_p(unsigned long long v) {
    return (int)(v >> 32);
}

// ---------------------------------------------------------------------------
// Phase 1: w = diff * sigmoid(_log_scaling(attrs) . weight[n] + bias[n]);
// init packed state {w, parent}. attrs staged to smem via float4.
// Fast transcendental intrinsics: logit error ~2e-6 (weights |w|<=0.01),
// invisible next to the fp16 output rounding (2e-4).
// ---------------------------------------------------------------------------
__global__ void __launch_bounds__(256) score_kernel(
    const float* __restrict__ diff, const float* __restrict__ attrs,
    const float* __restrict__ weight, const float* __restrict__ bias,
    const int* __restrict__ parent)
{
    __shared__ float sa[256 * NATTR];
    const int base = blockIdx.x * 256;
    const float4* ap = (const float4*)(attrs + (size_t)base * NATTR);
    #pragma unroll
    for (int k = threadIdx.x; k < 256 * NATTR / 4; k += 256)
        ((float4*)sa)[k] = ap[k];
    __syncthreads();

    const int idx = base + threadIdx.x;
    const float* f = &sa[threadIdx.x * NATTR];
    const int n = (idx >> 16) & (NN - 1);      // all 256 elems share one n
    const float* wg = weight + n * 17;

    // feats: [bbox0..3, log(area), signed-log f[6..14] (9), lshape, cos, sin]
    float logit = bias[n];
    logit += f[0] * wg[0] + f[1] * wg[1] + f[2] * wg[2] + f[3] * wg[3];
    logit += __logf(f[4]) * wg[4];
    #pragma unroll
    for (int k = 0; k < 9; k++) {
        float x = f[6 + k];
        float sg = (float)((x > 0.0f) - (x < 0.0f));
        logit += sg * __logf(fabsf(x) + EPSF) * wg[5 + k];
    }
    logit += __fdividef(__fsqrt_rn(f[7]), __fsqrt_rn(f[6]) + EPSF) * wg[14];
    float sn, cs;
    __sincosf(f[5], &sn, &cs);
    logit += cs * wg[15] + sn * wg[16];

    const float score = __fdividef(1.0f, 1.0f + __expf(-logit));
    g_sp[idx] = pack_sp(diff[idx] * score, parent[idx]);
}

// ---------------------------------------------------------------------------
// Phase 2a: in-smem chunk compression via racy path-compressing chain walks
// (8B untorn smem ops; entries only improve: p strictly decreases, invariant
// s = sum over [e,p) preserved). parent[i] < i guarantees termination.
// Chunk-0 blocks: every element ends fully rooted (cbase=0 -> escape only
// via p==NC), so they also write their fp16 finals to g_val directly; their
// compressed g_sp is still published (hop target for higher chunks).
// ---------------------------------------------------------------------------
__global__ void __launch_bounds__(CT) chunk_kernel() {
    extern __shared__ unsigned long long sp[];
    const int gbase = blockIdx.x * CK;
    const int cbase = gbase & (NC - 1);        // row-local chunk base
    const int clim  = cbase + CK;

    for (int j = threadIdx.x; j < CK / 2; j += CT)
        ((ulonglong2*)sp)[j] = ((const ulonglong2*)&g_sp[gbase])[j];
    __syncthreads();

    #pragma unroll
    for (int j = 0; j < CK / CT; j++) {
        const int e = threadIdx.x + j * CT;    // ascending: low elems first
        unsigned long long v = sp[e];
        float s = sp_s(v);
        int   p = sp_p(v);
        while (p >= cbase && p < clim) {       // in-chunk (excludes NC)
            unsigned long long q = sp[p - cbase];
            s += sp_s(q);
            p  = sp_p(q);                      // strictly decreasing
        }
        sp[e] = pack_sp(s, p);                 // publish compressed entry
    }
    __syncthreads();

    for (int j = threadIdx.x; j < CK / 2; j += CT)
        ((ulonglong2*)&g_sp[gbase])[j] = ((const ulonglong2*)sp)[j];

    if (cbase == 0) {                          // chunk 0: finals, write g_val
        for (int j = threadIdx.x; j < CK / 2; j += CT) {
            unsigned long long v0 = sp[j * 2], v1 = sp[j * 2 + 1];
            __half2 h = __floats2half2_rn(sp_s(v0) * 0.1f, sp_s(v1) * 0.1f);
            *(__half2*)&g_val[gbase + j * 2] = h;
        }
    }
}

// ---------------------------------------------------------------------------
// Phase 2b: extract for chunks 1..3 only (chunk 0 finalized in-place above).
// Bounded chain walk (depth <= 3); 4 lanes/thread for ILP; folds 1/SCALING.
// ---------------------------------------------------------------------------
__global__ void __launch_bounds__(256) extract_kernel() {
    const int t = blockIdx.x * 256 + threadIdx.x;
    const int q = t * 4;                       // index within chunks-1..3 space
    const int row = q / (3 * CK);
    const int off = q - row * (3 * CK);
    const int rowbase = row << 16;
    const int e0 = rowbase + CK + off;         // 4 consecutive elems, same row

    ulonglong2 a = __ldcg((const ulonglong2*)&g_sp[e0]);
    ulonglong2 b = __ldcg((const ulonglong2*)&g_sp[e0 + 2]);

    float s0 = sp_s(a.x), s1 = sp_s(a.y), s2 = sp_s(b.x), s3 = sp_s(b.y);
    int   p0 = sp_p(a.x), p1 = sp_p(a.y), p2 = sp_p(b.x), p3 = sp_p(b.y);

    #pragma unroll
    for (int it = 0; it < 3; it++) {
        unsigned long long q0 = (p0 != NC) ? __ldcg(&g_sp[rowbase + p0]) : 0ull;
        unsigned long long q1 = (p1 != NC) ? __ldcg(&g_sp[rowbase + p1]) : 0ull;
        unsigned long long q2 = (p2 != NC) ? __ldcg(&g_sp[rowbase + p2]) : 0ull;
        unsigned long long q3 = (p3 != NC) ? __ldcg(&g_sp[rowbase + p3]) : 0ull;
        if (p0 != NC) { s0 += sp_s(q0); p0 = sp_p(q0); }
        if (p1 != NC) { s1 += sp_s(q1); p1 = sp_p(q1); }
        if (p2 != NC) { s2 += sp_s(q2); p2 = sp_p(q2); }
        if (p3 != NC) { s3 += sp_s(q3); p3 = sp_p(q3); }
    }

    __half2 h01 = __floats2half2_rn(s0 * 0.1f, s1 * 0.1f);
    __half2 h23 = __floats2half2_rn(s2 * 0.1f, s3 * 0.1f);
    uint2 o;
    o.x = *(unsigned int*)&h01;
    o.y = *(unsigned int*)&h23;
    *(uint2*)&g_val[e0] = o;
}

// ---------------------------------------------------------------------------
// Phase 3: smem-windowed gather (measured 14.5us config). One block per
// (row, slice); full 65536-entry fp16 window (128 KB) in dynamic smem.
// 1024 threads (32 warps/SM); 128 blocks = one clean wave.
// ---------------------------------------------------------------------------
__global__ void __launch_bounds__(1024) gather_kernel(
    const int* __restrict__ pix2cc, float* __restrict__ out)
{
    extern __shared__ __half sv[];
    const int row = blockIdx.x >> 2;                 // GSLICE = 4
    const int pbase = blockIdx.x << 16;              // 65536 pixels per block

    const uint4* vals = (const uint4*)(g_val + (row << 16));
    #pragma unroll
    for (int i = threadIdx.x; i < NC * 2 / 16; i += 1024)
        ((uint4*)sv)[i] = __ldcg(&vals[i]);
    __syncthreads();

    const int4* pc = (const int4*)(pix2cc + pbase);
    float4* op = (float4*)(out + pbase);
    #pragma unroll
    for (int i = threadIdx.x; i < 65536 / 4; i += 1024) {
        const int4 cc = __ldg(&pc[i]);
        float4 o;
        o.x = __half2float(sv[cc.x]);
        o.y = __half2float(sv[cc.y]);
        o.z = __half2float(sv[cc.z]);
        o.w = __half2float(sv[cc.w]);
        op[i] = o;
    }
}

// ---------------------------------------------------------------------------
extern "C" void kernel_launch(void* const* d_in, const int* in_sizes, int n_in,
                              void* d_out, int out_size) {
    const float* diff   = (const float*)d_in[0];
    const float* attrs  = (const float*)d_in[1];
    const float* weight = (const float*)d_in[2];
    const float* bias   = (const float*)d_in[3];
    const int*   parent = (const int*)d_in[4];
    const int*   pix2cc = (const int*)d_in[5];
    float* out = (float*)d_out;

    const int chunk_smem  = CK * 8;       // 128 KB
    const int gather_smem = NC * 2;       // 128 KB
    cudaFuncSetAttribute(chunk_kernel,
                         cudaFuncAttributeMaxDynamicSharedMemorySize, chunk_smem);
    cudaFuncSetAttribute(gather_kernel,
                         cudaFuncAttributeMaxDynamicSharedMemorySize, gather_smem);

    score_kernel<<<TOT / 256, 256>>>(diff, attrs, weight, bias, parent);
    chunk_kernel<<<TOT / CK, CT, chunk_smem>>>();
    extract_kernel<<<TOT3 / 1024, 256>>>();
    gather_kernel<<<NB * NN * GSLICE, 1024, gather_smem>>>(pix2cc, out);
}